// round 15
// baseline (speedup 1.0000x reference)
#include <cuda_runtime.h>
#include <math.h>
#include <stdint.h>

#define SEQL    4096
#define BATCHN  4
#define BL      (BATCHN*SEQL)       // 16384
#define DMODEL  192
#define DINNER  384
#define DSTATE  64
#define NHEADS  8
#define HEADDIM 48
#define CONVDIM 512
#define DINPROJ 904
#define NLAYERS 8
#define NCHUNK  64
#define CHUNKL  64

// ---------------- scratch (device globals) -------------------------------
__device__ float g_X[BL*DMODEL];
__device__ float g_ZX[BL*DINPROJ];
__device__ float g_CONV[BL*CONVDIM];
__device__ float g_DTDEC[BL*NHEADS*2];
__device__ float g_Y[BL*DINNER];
__device__ float g_O[BL*DMODEL];
__device__ float g_S[BATCHN*NHEADS*NCHUNK*HEADDIM*DSTATE];
__device__ float g_P[BATCHN*NHEADS*NCHUNK];
__device__ float g_LAM[BL*NHEADS];

__device__ __forceinline__ float sigf(float x){ return 1.f/(1.f+__expf(-x)); }

__device__ __forceinline__ float f2tf32(float x) {
    uint32_t o;
    asm("cvt.rna.tf32.f32 %0, %1;" : "=r"(o) : "f"(x));
    return __uint_as_float(o);
}

// ---------------- input linear -------------------------------------------
__global__ void k_lin_in(const float* __restrict__ inp,
                         const float* __restrict__ w,
                         const float* __restrict__ bias) {
    int idx = blockIdx.x*blockDim.x + threadIdx.x;
    if (idx >= BL*DMODEL) return;
    int d  = idx % DMODEL;
    int bl = idx / DMODEL;
    int b = bl / SEQL, l = bl % SEQL;
    const float* ip = inp + (size_t)b*3*SEQL + l;
    float acc = bias[d];
    acc = fmaf(ip[0],      w[d*3+0], acc);
    acc = fmaf(ip[SEQL],   w[d*3+1], acc);
    acc = fmaf(ip[2*SEQL], w[d*3+2], acc);
    g_X[idx] = fmaxf(acc, 0.f);
}

// ---------------- 3xTF32 GEMM, double-buffered, hi/lo packed -------------
// mode 0: A=g_X, C=g_ZX+cofs ; mode 1: A=g_Y, C=g_O. W pre-offset by caller.
#define SA(b,k,m) sA[(((b)*16+(k))*132)+(m)]
#define SB(b,k,m) sB[(((b)*16+(k))*132)+(m)]

__global__ __launch_bounds__(256, 2)
void k_mma(const float* __restrict__ W, int mode, int N, int K, int ldC,
           int cofs) {
    const float* A;
    float* C;
    if (mode == 0) { A = g_X; C = g_ZX + cofs; } else { A = g_Y; C = g_O; }

    extern __shared__ float2 smem[];
    float2* sA = smem;
    float2* sB = smem + 2*16*132;

    const int nbx = (N + 127)/128;
    const int bm = (blockIdx.x / nbx) * 128;
    const int bn = (blockIdx.x % nbx) * 128;
    const int tid  = threadIdx.x;
    const int lane = tid & 31;
    const int wid  = tid >> 5;
    const int wm = wid >> 2;
    const int wn = wid & 3;
    const int lg = lane >> 2;
    const int lt = lane & 3;

    float acc[4][4][4];
    #pragma unroll
    for (int i = 0; i < 4; i++)
        #pragma unroll
        for (int j = 0; j < 4; j++)
            #pragma unroll
            for (int r = 0; r < 4; r++) acc[i][j][r] = 0.f;

    const int fr = tid >> 1;
    const int fh = (tid & 1) * 8;
    const bool wvalid = (bn + fr) < N;
    const float* Ag = A + (size_t)(bm + fr)*K + fh;
    const float* Wg = wvalid ? (W + (size_t)(bn + fr)*K + fh) : W;

    float av[8], bv[8];
    const int KT = K / 16;

    {
        float4 t0 = *(const float4*)(Ag + 0);
        float4 t1 = *(const float4*)(Ag + 4);
        av[0]=t0.x; av[1]=t0.y; av[2]=t0.z; av[3]=t0.w;
        av[4]=t1.x; av[5]=t1.y; av[6]=t1.z; av[7]=t1.w;
        if (wvalid) {
            float4 u0 = *(const float4*)(Wg + 0);
            float4 u1 = *(const float4*)(Wg + 4);
            bv[0]=u0.x; bv[1]=u0.y; bv[2]=u0.z; bv[3]=u0.w;
            bv[4]=u1.x; bv[5]=u1.y; bv[6]=u1.z; bv[7]=u1.w;
        } else {
            #pragma unroll
            for (int q = 0; q < 8; q++) bv[q] = 0.f;
        }
    }
    #pragma unroll
    for (int q = 0; q < 8; q++) {
        float ah = f2tf32(av[q]);
        SA(0, fh+q, fr) = make_float2(ah, f2tf32(av[q] - ah));
        float bh = f2tf32(bv[q]);
        SB(0, fh+q, fr) = make_float2(bh, f2tf32(bv[q] - bh));
    }
    __syncthreads();

    for (int kt = 0; kt < KT; kt++) {
        const int buf = kt & 1;
        if (kt + 1 < KT) {
            const float* an = Ag + (kt+1)*16;
            float4 t0 = *(const float4*)(an + 0);
            float4 t1 = *(const float4*)(an + 4);
            av[0]=t0.x; av[1]=t0.y; av[2]=t0.z; av[3]=t0.w;
            av[4]=t1.x; av[5]=t1.y; av[6]=t1.z; av[7]=t1.w;
            if (wvalid) {
                const float* wv = Wg + (kt+1)*16;
                float4 u0 = *(const float4*)(wv + 0);
                float4 u1 = *(const float4*)(wv + 4);
                bv[0]=u0.x; bv[1]=u0.y; bv[2]=u0.z; bv[3]=u0.w;
                bv[4]=u1.x; bv[5]=u1.y; bv[6]=u1.z; bv[7]=u1.w;
            }
        }

        #pragma unroll
        for (int ks = 0; ks < 2; ks++) {
            const int kr = ks*8 + lt;
            float2 bf[4][2];
            #pragma unroll
            for (int j = 0; j < 4; j++) {
                int n0 = wn*32 + j*8 + lg;
                bf[j][0] = SB(buf, kr,   n0);
                bf[j][1] = SB(buf, kr+4, n0);
            }
            #pragma unroll
            for (int i = 0; i < 4; i++) {
                int m0 = wm*64 + i*16 + lg;
                float2 a0 = SA(buf, kr,   m0);
                float2 a1 = SA(buf, kr,   m0+8);
                float2 a2 = SA(buf, kr+4, m0);
                float2 a3 = SA(buf, kr+4, m0+8);
                uint32_t ah0 = __float_as_uint(a0.x), al0 = __float_as_uint(a0.y);
                uint32_t ah1 = __float_as_uint(a1.x), al1 = __float_as_uint(a1.y);
                uint32_t ah2 = __float_as_uint(a2.x), al2 = __float_as_uint(a2.y);
                uint32_t ah3 = __float_as_uint(a3.x), al3 = __float_as_uint(a3.y);
                #pragma unroll
                for (int j = 0; j < 4; j++) {
                    uint32_t bh0 = __float_as_uint(bf[j][0].x);
                    uint32_t bh1 = __float_as_uint(bf[j][1].x);
                    uint32_t bl0 = __float_as_uint(bf[j][0].y);
                    uint32_t bl1 = __float_as_uint(bf[j][1].y);
                    asm volatile(
                        "mma.sync.aligned.m16n8k8.row.col.f32.tf32.tf32.f32 "
                        "{%0,%1,%2,%3}, {%4,%5,%6,%7}, {%8,%9}, {%0,%1,%2,%3};"
                        : "+f"(acc[i][j][0]), "+f"(acc[i][j][1]),
                          "+f"(acc[i][j][2]), "+f"(acc[i][j][3])
                        : "r"(al0), "r"(al1), "r"(al2), "r"(al3),
                          "r"(bh0), "r"(bh1));
                    asm volatile(
                        "mma.sync.aligned.m16n8k8.row.col.f32.tf32.tf32.f32 "
                        "{%0,%1,%2,%3}, {%4,%5,%6,%7}, {%8,%9}, {%0,%1,%2,%3};"
                        : "+f"(acc[i][j][0]), "+f"(acc[i][j][1]),
                          "+f"(acc[i][j][2]), "+f"(acc[i][j][3])
                        : "r"(ah0), "r"(ah1), "r"(ah2), "r"(ah3),
                          "r"(bl0), "r"(bl1));
                    asm volatile(
                        "mma.sync.aligned.m16n8k8.row.col.f32.tf32.tf32.f32 "
                        "{%0,%1,%2,%3}, {%4,%5,%6,%7}, {%8,%9}, {%0,%1,%2,%3};"
                        : "+f"(acc[i][j][0]), "+f"(acc[i][j][1]),
                          "+f"(acc[i][j][2]), "+f"(acc[i][j][3])
                        : "r"(ah0), "r"(ah1), "r"(ah2), "r"(ah3),
                          "r"(bh0), "r"(bh1));
                }
            }
        }

        if (kt + 1 < KT) {
            const int nb = 1 - buf;
            #pragma unroll
            for (int q = 0; q < 8; q++) {
                float ah = f2tf32(av[q]);
                SA(nb, fh+q, fr) = make_float2(ah, f2tf32(av[q] - ah));
                float bh = f2tf32(bv[q]);
                SB(nb, fh+q, fr) = make_float2(bh, f2tf32(bv[q] - bh));
            }
        }
        __syncthreads();
    }

    #pragma unroll
    for (int i = 0; i < 4; i++) {
        int m = bm + wm*64 + i*16 + lg;
        #pragma unroll
        for (int j = 0; j < 4; j++) {
            int n = bn + wn*32 + j*8 + 2*lt;
            if (n < N) {
                *(float2*)&C[(size_t)m*ldC + n] =
                    make_float2(acc[i][j][0], acc[i][j][1]);
                *(float2*)&C[(size_t)(m+8)*ldC + n] =
                    make_float2(acc[i][j][2], acc[i][j][3]);
            }
        }
    }
}
#define MMA_SMEM (2*2*16*132*sizeof(float2))

// -------- fused: causal conv4+silu  AND  elementwise dt (appended) -------
#define CONV_BLKS ((BL*CONVDIM + 255)/256)   // 32768
#define DT_BLKS   ((BL*NHEADS + 255)/256)    // 512

__global__ __launch_bounds__(256)
void k_convdt(const float* __restrict__ conv_w, const float* __restrict__ conv_b,
              const float* __restrict__ dt_bias, const float* __restrict__ A_log) {
    if (blockIdx.x >= CONV_BLKS) {
        // dt path: raw dt columns already in g_ZX (3xTF32 GEMM)
        int idx = (blockIdx.x - CONV_BLKS)*256 + threadIdx.x;
        if (idx >= BL*NHEADS) return;
        int h  = idx & 7;
        int bl = idx >> 3;
        float raw = g_ZX[(size_t)bl*DINPROJ + 896 + h] + dt_bias[h];
        float dt = (raw > 20.f) ? raw : log1pf(__expf(raw));
        float Ah = -__expf(A_log[h]);
        g_DTDEC[bl*16 + 2*h    ] = dt;
        g_DTDEC[bl*16 + 2*h + 1] = __expf(dt * Ah);
        return;
    }
    int idx = blockIdx.x*blockDim.x + threadIdx.x;
    int c  = idx & (CONVDIM-1);
    int bl = idx >> 9;
    int l  = bl & (SEQL-1);
    float acc = conv_b[c];
    const float* base = &g_ZX[(size_t)bl*DINPROJ + 384 + c];
    #pragma unroll
    for (int k = 0; k < 4; k++) {
        int ll = l - 3 + k;
        if (ll >= 0)
            acc = fmaf(base[(ptrdiff_t)(k-3)*DINPROJ], conv_w[c*4 + k], acc);
    }
    g_CONV[idx] = acc * sigf(acc);
}

// ================= block-cooperative chunked scan =========================
#define SCAN_SMEM (64*128*4 + 64*48*4 + 64*8)   // 45568 B

__global__ __launch_bounds__(384, 4)
void k_scan_blk(const float* __restrict__ Dvec) {
    extern __shared__ float sm[];
    float*  sBC  = sm;                 // [64][128]
    float*  sX   = sBC + 64*128;       // [64][48]
    float2* sdde = (float2*)(sX + 64*48);  // [64]

    int ck = blockIdx.x & (NCHUNK-1);
    int bh = blockIdx.x >> 6;
    int h  = bh & 7, b = bh >> 3;
    int bl0 = b*SEQL + ck*CHUNKL;
    int tid  = threadIdx.x;
    int lane = tid & 31;
    int wid  = tid >> 5;
    int p0   = wid*4;

    const float* convb = g_CONV + (size_t)bl0*CONVDIM;

    for (int q = tid; q < 64*32; q += 384) {
        int t = q >> 5, c4 = (q & 31) << 2;
        *(float4*)&sBC[t*128 + c4] =
            *(const float4*)&convb[(size_t)t*CONVDIM + 384 + c4];
    }
    for (int q = tid; q < 64*12; q += 384) {
        int t = q / 12, c4 = (q % 12) << 2;
        *(float4*)&sX[t*48 + c4] =
            *(const float4*)&convb[(size_t)t*CONVDIM + h*HEADDIM + c4];
    }
    if (tid < 64)
        sdde[tid] = *(const float2*)&g_DTDEC[(size_t)(bl0 + tid)*16 + 2*h];
    __syncthreads();

    if (tid == 0) {
        float pr = 1.f;
        for (int t = 0; t < CHUNKL; t++) {
            pr *= sdde[t].y;
            g_LAM[(size_t)(bl0 + t)*NHEADS + h] = pr;
        }
        g_P[bh*NCHUNK + ck] = pr;
    }

    const float Dh = Dvec[h];
    const int g    = lane >> 3;
    const int poff = (g >> 1) | ((g & 1) << 1);
    const bool st  = (lane & 7) == 0;
    float* yo = g_Y + (size_t)bl0*DINNER + h*HEADDIM + p0 + poff;

    float h0[4], h1[4];
    #pragma unroll
    for (int i = 0; i < 4; i++) { h0[i] = 0.f; h1[i] = 0.f; }

    #pragma unroll 2
    for (int t = 0; t < CHUNKL; t++) {
        float2 dde = sdde[t];
        float4 xv  = *(const float4*)&sX[t*48 + p0];
        float2 Bv  = *(const float2*)&sBC[t*128 + 2*lane];
        float2 Cv  = *(const float2*)&sBC[t*128 + 64 + 2*lane];
        float bx = dde.x * Bv.x;
        float by = dde.x * Bv.y;
        float xa[4] = {xv.x, xv.y, xv.z, xv.w};
        float y[4];
        #pragma unroll
        for (int i = 0; i < 4; i++) {
            h0[i] = fmaf(h0[i], dde.y, xa[i]*bx);
            h1[i] = fmaf(h1[i], dde.y, xa[i]*by);
            y[i]  = fmaf(h0[i], Cv.x, h1[i]*Cv.y);
        }
        #pragma unroll
        for (int i = 0; i < 4; i++)
            y[i] += __shfl_xor_sync(0xffffffffu, y[i], 16);
        float za = (lane & 16) ? y[1] : y[0];
        float zb = (lane & 16) ? y[3] : y[2];
        za += __shfl_xor_sync(0xffffffffu, za, 8);
        zb += __shfl_xor_sync(0xffffffffu, zb, 8);
        float wv = (lane & 8) ? zb : za;
        wv += __shfl_xor_sync(0xffffffffu, wv, 4);
        wv += __shfl_xor_sync(0xffffffffu, wv, 2);
        wv += __shfl_xor_sync(0xffffffffu, wv, 1);
        if (st) {
            float xs = (g == 0) ? xa[0] : (g == 1) ? xa[2]
                     : (g == 2) ? xa[1] : xa[3];
            *yo = fmaf(Dh, xs, wv);
        }
        yo += DINNER;
    }

    float* S = &g_S[((((size_t)bh*NCHUNK + ck)*HEADDIM) + p0)*DSTATE + 2*lane];
    #pragma unroll
    for (int i = 0; i < 4; i++)
        *(float2*)(S + (size_t)i*DSTATE) = make_float2(h0[i], h1[i]);
}

// inter-chunk recurrence — register-staged
__global__ __launch_bounds__(256)
void k_chunk_seq() {
    int idx = blockIdx.x*blockDim.x + threadIdx.x;
    if (idx >= BATCHN*NHEADS*HEADDIM*DSTATE) return;
    int pn = idx % (HEADDIM*DSTATE);
    int bh = idx / (HEADDIM*DSTATE);
    const float* P = g_P + bh*NCHUNK;
    float* S = g_S + (size_t)bh*NCHUNK*HEADDIM*DSTATE + pn;

    float v[NCHUNK];
    #pragma unroll
    for (int k = 0; k < NCHUNK; k++)
        v[k] = __ldg(S + (size_t)k*HEADDIM*DSTATE);

    float h = 0.f;
    #pragma unroll
    for (int k = 0; k < NCHUNK; k++) {
        float s = v[k];
        v[k] = h;
        h = fmaf(h, P[k], s);
    }

    #pragma unroll
    for (int k = 0; k < NCHUNK; k++)
        S[(size_t)k*HEADDIM*DSTATE] = v[k];
}

// correction: Y[t][p] += Lam_t * sum_n C[t][n] * Hinit[p][n]
__global__ __launch_bounds__(256)
void k_corr() {
    __shared__ float Cs[64][68];
    __shared__ float Hs[64][49];
    __shared__ float Ls[64];

    int ck = blockIdx.x % NCHUNK;
    int bh = blockIdx.x / NCHUNK;
    int h  = bh & 7, b = bh >> 3;
    int bl0 = b*SEQL + ck*CHUNKL;
    int tid = threadIdx.x;

    #pragma unroll
    for (int q = tid; q < 64*16; q += 256) {
        int t  = q >> 4;
        int n4 = (q & 15) << 2;
        float4 v = *(const float4*)&g_CONV[(size_t)(bl0 + t)*CONVDIM + 448 + n4];
        Cs[n4+0][t] = v.x; Cs[n4+1][t] = v.y;
        Cs[n4+2][t] = v.z; Cs[n4+3][t] = v.w;
    }
    const float* Sb = g_S + (((size_t)bh*NCHUNK + ck)*HEADDIM)*DSTATE;
    #pragma unroll
    for (int q = tid; q < 48*16; q += 256) {
        int p  = q >> 4;
        int n4 = (q & 15) << 2;
        float4 v = *(const float4*)&Sb[(size_t)p*DSTATE + n4];
        Hs[n4+0][p] = v.x; Hs[n4+1][p] = v.y;
        Hs[n4+2][p] = v.z; Hs[n4+3][p] = v.w;
    }
    if (tid < 64)
        Ls[tid] = g_LAM[(size_t)(bl0 + tid)*NHEADS + h];
    __syncthreads();

    int tx = tid & 15, ty = tid >> 4;
    int pp = tx*3, tt = ty*4;

    float acc[4][3];
    #pragma unroll
    for (int i = 0; i < 4; i++)
        #pragma unroll
        for (int j = 0; j < 3; j++) acc[i][j] = 0.f;

    #pragma unroll 4
    for (int n = 0; n < 64; n++) {
        float4 c = *(const float4*)&Cs[n][tt];
        float ca[4] = {c.x, c.y, c.z, c.w};
        float hh0 = Hs[n][pp], hh1 = Hs[n][pp+1], hh2 = Hs[n][pp+2];
        #pragma unroll
        for (int i = 0; i < 4; i++) {
            acc[i][0] = fmaf(ca[i], hh0, acc[i][0]);
            acc[i][1] = fmaf(ca[i], hh1, acc[i][1]);
            acc[i][2] = fmaf(ca[i], hh2, acc[i][2]);
        }
    }

    #pragma unroll
    for (int i = 0; i < 4; i++) {
        float lam = Ls[tt + i];
        float* yr = g_Y + (size_t)(bl0 + tt + i)*DINNER + h*HEADDIM + pp;
        #pragma unroll
        for (int j = 0; j < 3; j++)
            yr[j] = fmaf(lam, acc[i][j], yr[j]);
    }
}

// ---------------- gated RMSNorm ------------------------------------------
__global__ __launch_bounds__(128)
void k_gated_rms(const float* __restrict__ norm_w) {
    int bl = blockIdx.x;
    int t  = threadIdx.x;
    int lane = t & 31, wid = t >> 5;
    __shared__ float sh[4];
    float v[3];
    float ss = 0.f;
    #pragma unroll
    for (int j = 0; j < 3; j++) {
        int d = t + j*128;
        float y = g_Y[(size_t)bl*DINNER + d];
        float z = g_ZX[(size_t)bl*DINPROJ + d];
        y *= z * sigf(z);
        v[j] = y;
        ss = fmaf(y, y, ss);
    }
    #pragma unroll
    for (int o = 16; o > 0; o >>= 1) ss += __shfl_xor_sync(0xffffffffu, ss, o);
    if (lane == 0) sh[wid] = ss;
    __syncthreads();
    ss = sh[0] + sh[1] + sh[2] + sh[3];
    float rms = rsqrtf(ss * (1.f/DINNER) + 1e-5f);
    #pragma unroll
    for (int j = 0; j < 3; j++) {
        int d = t + j*128;
        g_Y[(size_t)bl*DINNER + d] = v[j] * rms * norm_w[d];
    }
}

// ---------------- residual add + layernorm -> X --------------------------
__global__ __launch_bounds__(192)
void k_res_ln(const float* __restrict__ ln_w, const float* __restrict__ ln_b) {
    int bl = blockIdx.x;
    int d  = threadIdx.x;
    int lane = d & 31, wid = d >> 5;
    __shared__ float shs[6], shq[6];
    float x = g_O[(size_t)bl*DMODEL + d] + g_X[(size_t)bl*DMODEL + d];
    float s = x, q = x*x;
    #pragma unroll
    for (int o = 16; o > 0; o >>= 1) {
        s += __shfl_xor_sync(0xffffffffu, s, o);
        q += __shfl_xor_sync(0xffffffffu, q, o);
    }
    if (lane == 0) { shs[wid] = s; shq[wid] = q; }
    __syncthreads();
    s = 0.f; q = 0.f;
    #pragma unroll
    for (int i = 0; i < 6; i++) { s += shs[i]; q += shq[i]; }
    float mu  = s * (1.f/DMODEL);
    float var = q * (1.f/DMODEL) - mu*mu;
    g_X[(size_t)bl*DMODEL + d] = (x - mu) * rsqrtf(var + 1e-5f) * ln_w[d] + ln_b[d];
}

// ---------------- output linear ------------------------------------------
__global__ __launch_bounds__(192)
void k_final(const float* __restrict__ w, const float* __restrict__ bias,
             float* __restrict__ out) {
    int bl = blockIdx.x;
    int d  = threadIdx.x;
    int lane = d & 31, wid = d >> 5;
    int b = bl / SEQL, l = bl % SEQL;
    __shared__ float sh[6][4];
    float x = g_X[(size_t)bl*DMODEL + d];
    float p0 = x * w[0*DMODEL + d];
    float p1 = x * w[1*DMODEL + d];
    float p2 = x * w[2*DMODEL + d];
    float p3 = x * w[3*DMODEL + d];
    #pragma unroll
    for (int o = 16; o > 0; o >>= 1) {
        p0 += __shfl_xor_sync(0xffffffffu, p0, o);
        p1 += __shfl_xor_sync(0xffffffffu, p1, o);
        p2 += __shfl_xor_sync(0xffffffffu, p2, o);
        p3 += __shfl_xor_sync(0xffffffffu, p3, o);
    }
    if (lane == 0) { sh[wid][0]=p0; sh[wid][1]=p1; sh[wid][2]=p2; sh[wid][3]=p3; }
    __syncthreads();
    if (d < 4) {
        float s = 0.f;
        #pragma unroll
        for (int i = 0; i < 6; i++) s += sh[i][d];
        out[(size_t)b*4*SEQL + (size_t)d*SEQL + l] = s + bias[d];
    }
}

// ---------------- driver --------------------------------------------------
extern "C" void kernel_launch(void* const* d_in, const int* in_sizes, int n_in,
                              void* d_out, int out_size) {
    const float* inp      = (const float*)d_in[0];
    const float* lin_in_w = (const float*)d_in[1];
    const float* lin_in_b = (const float*)d_in[2];
    const float* in_w     = (const float*)d_in[3];
    const float* conv_w   = (const float*)d_in[4];
    const float* conv_b   = (const float*)d_in[5];
    const float* dt_bias  = (const float*)d_in[6];
    const float* A_log    = (const float*)d_in[7];
    const float* Dv       = (const float*)d_in[8];
    const float* norm_w   = (const float*)d_in[9];
    const float* out_w    = (const float*)d_in[10];
    const float* ln_w     = (const float*)d_in[11];
    const float* ln_b     = (const float*)d_in[12];
    const float* lo_w     = (const float*)d_in[13];
    const float* lo_b     = (const float*)d_in[14];
    float* out = (float*)d_out;

    static cudaStream_t s2 = nullptr;
    static cudaEvent_t evA = nullptr, evC = nullptr;
    if (!s2) {
        cudaStreamCreateWithFlags(&s2, cudaStreamNonBlocking);
        cudaEventCreateWithFlags(&evA, cudaEventDisableTiming);
        cudaEventCreateWithFlags(&evC, cudaEventDisableTiming);
        cudaFuncSetAttribute(k_mma, cudaFuncAttributeMaxDynamicSharedMemorySize,
                             (int)MMA_SMEM);
        cudaFuncSetAttribute(k_scan_blk, cudaFuncAttributeMaxDynamicSharedMemorySize,
                             (int)SCAN_SMEM);
    }

    const int scan_blocks = BATCHN*NHEADS*NCHUNK;   // 2048
    const int corr_blocks = BATCHN*NHEADS*NCHUNK;

    k_lin_in<<<(BL*DMODEL + 255)/256, 256>>>(inp, lin_in_w, lin_in_b);

    for (int layer = 0; layer < NLAYERS; layer++) {
        const float* in_w_l = in_w + (size_t)layer*DINPROJ*DMODEL;

        // in_proj A: xBC + dt columns [384, 904) -> N=520, cofs=384
        {
            int nbx = (520 + 127)/128;   // 5
            k_mma<<<nbx*(BL/128), 256, MMA_SMEM>>>(
                in_w_l + (size_t)384*DMODEL, 0, 520, DMODEL, DINPROJ, 384);
        }
        cudaEventRecord(evA, 0);

        // in_proj B: z columns [0, 384) on stream 0 (overlaps s2 chain)
        {
            int nbx = 384/128;           // 3
            k_mma<<<nbx*(BL/128), 256, MMA_SMEM>>>(
                in_w_l, 0, 384, DMODEL, DINPROJ, 0);
        }

        // s2 chain: conv+dt -> scan -> chunk_seq -> corr
        cudaStreamWaitEvent(s2, evA, 0);
        k_convdt<<<CONV_BLKS + DT_BLKS, 256, 0, s2>>>(
            conv_w + (size_t)layer*CONVDIM*4,
            conv_b + (size_t)layer*CONVDIM,
            dt_bias + layer*NHEADS,
            A_log + layer*NHEADS);
        k_scan_blk<<<scan_blocks, 384, SCAN_SMEM, s2>>>(Dv + layer*NHEADS);
        k_chunk_seq<<<(BATCHN*NHEADS*HEADDIM*DSTATE + 255)/256, 256, 0, s2>>>();
        k_corr<<<corr_blocks, 256, 0, s2>>>();
        cudaEventRecord(evC, s2);

        // join; gated RMS needs z (stream 0) + corrected Y (s2)
        cudaStreamWaitEvent(0, evC, 0);
        k_gated_rms<<<BL, 128>>>(norm_w + (size_t)layer*DINNER);
        {
            int nbx = (DMODEL + 127)/128;  // 2
            k_mma<<<nbx*(BL/128), 256, MMA_SMEM>>>(
                out_w + (size_t)layer*DMODEL*DINNER, 1, DMODEL, DINNER,
                DMODEL, 0);
        }
        k_res_ln<<<BL, 192>>>(ln_w + (size_t)layer*DMODEL,
                              ln_b + (size_t)layer*DMODEL);
    }

    k_final<<<BL, 192>>>(lo_w, lo_b, out);
}

// round 16
// speedup vs baseline: 1.0114x; 1.0114x over previous
#include <cuda_runtime.h>
#include <math.h>
#include <stdint.h>

#define SEQL    4096
#define BATCHN  4
#define BL      (BATCHN*SEQL)       // 16384
#define DMODEL  192
#define DINNER  384
#define DSTATE  64
#define NHEADS  8
#define HEADDIM 48
#define CONVDIM 512
#define DINPROJ 904
#define NLAYERS 8
#define NCHUNK  64
#define CHUNKL  64

// ---------------- scratch (device globals) -------------------------------
__device__ float g_X[BL*DMODEL];
__device__ float g_ZX[BL*DINPROJ];
__device__ float g_CONV[BL*CONVDIM];
__device__ float g_DTDEC[BL*NHEADS*2];
__device__ float g_Y[BL*DINNER];
__device__ float g_O[BL*DMODEL];
__device__ float g_S[BATCHN*NHEADS*NCHUNK*HEADDIM*DSTATE];
__device__ float g_P[BATCHN*NHEADS*NCHUNK];
__device__ float g_LAM[BL*NHEADS];

__device__ __forceinline__ float sigf(float x){ return 1.f/(1.f+__expf(-x)); }

__device__ __forceinline__ float f2tf32(float x) {
    uint32_t o;
    asm("cvt.rna.tf32.f32 %0, %1;" : "=r"(o) : "f"(x));
    return __uint_as_float(o);
}

// ---------------- input linear -------------------------------------------
__global__ void k_lin_in(const float* __restrict__ inp,
                         const float* __restrict__ w,
                         const float* __restrict__ bias) {
    int idx = blockIdx.x*blockDim.x + threadIdx.x;
    if (idx >= BL*DMODEL) return;
    int d  = idx % DMODEL;
    int bl = idx / DMODEL;
    int b = bl / SEQL, l = bl % SEQL;
    const float* ip = inp + (size_t)b*3*SEQL + l;
    float acc = bias[d];
    acc = fmaf(ip[0],      w[d*3+0], acc);
    acc = fmaf(ip[SEQL],   w[d*3+1], acc);
    acc = fmaf(ip[2*SEQL], w[d*3+2], acc);
    g_X[idx] = fmaxf(acc, 0.f);
}

// ---------------- 3xTF32 GEMM, double-buffered, hi/lo packed -------------
// mode 0: A=g_X, C=g_ZX+cofs ; mode 1: A=g_Y, C=g_O. W pre-offset by caller.
#define SA(b,k,m) sA[(((b)*16+(k))*132)+(m)]
#define SB(b,k,m) sB[(((b)*16+(k))*132)+(m)]

__global__ __launch_bounds__(256, 2)
void k_mma(const float* __restrict__ W, int mode, int N, int K, int ldC,
           int cofs) {
    const float* A;
    float* C;
    if (mode == 0) { A = g_X; C = g_ZX + cofs; } else { A = g_Y; C = g_O; }

    extern __shared__ float2 smem[];
    float2* sA = smem;
    float2* sB = smem + 2*16*132;

    const int nbx = (N + 127)/128;
    const int bm = (blockIdx.x / nbx) * 128;
    const int bn = (blockIdx.x % nbx) * 128;
    const int tid  = threadIdx.x;
    const int lane = tid & 31;
    const int wid  = tid >> 5;
    const int wm = wid >> 2;
    const int wn = wid & 3;
    const int lg = lane >> 2;
    const int lt = lane & 3;

    float acc[4][4][4];
    #pragma unroll
    for (int i = 0; i < 4; i++)
        #pragma unroll
        for (int j = 0; j < 4; j++)
            #pragma unroll
            for (int r = 0; r < 4; r++) acc[i][j][r] = 0.f;

    const int fr = tid >> 1;
    const int fh = (tid & 1) * 8;
    const bool wvalid = (bn + fr) < N;
    const float* Ag = A + (size_t)(bm + fr)*K + fh;
    const float* Wg = wvalid ? (W + (size_t)(bn + fr)*K + fh) : W;

    float av[8], bv[8];
    const int KT = K / 16;

    {
        float4 t0 = *(const float4*)(Ag + 0);
        float4 t1 = *(const float4*)(Ag + 4);
        av[0]=t0.x; av[1]=t0.y; av[2]=t0.z; av[3]=t0.w;
        av[4]=t1.x; av[5]=t1.y; av[6]=t1.z; av[7]=t1.w;
        if (wvalid) {
            float4 u0 = *(const float4*)(Wg + 0);
            float4 u1 = *(const float4*)(Wg + 4);
            bv[0]=u0.x; bv[1]=u0.y; bv[2]=u0.z; bv[3]=u0.w;
            bv[4]=u1.x; bv[5]=u1.y; bv[6]=u1.z; bv[7]=u1.w;
        } else {
            #pragma unroll
            for (int q = 0; q < 8; q++) bv[q] = 0.f;
        }
    }
    #pragma unroll
    for (int q = 0; q < 8; q++) {
        float ah = f2tf32(av[q]);
        SA(0, fh+q, fr) = make_float2(ah, f2tf32(av[q] - ah));
        float bh = f2tf32(bv[q]);
        SB(0, fh+q, fr) = make_float2(bh, f2tf32(bv[q] - bh));
    }
    __syncthreads();

    for (int kt = 0; kt < KT; kt++) {
        const int buf = kt & 1;
        if (kt + 1 < KT) {
            const float* an = Ag + (kt+1)*16;
            float4 t0 = *(const float4*)(an + 0);
            float4 t1 = *(const float4*)(an + 4);
            av[0]=t0.x; av[1]=t0.y; av[2]=t0.z; av[3]=t0.w;
            av[4]=t1.x; av[5]=t1.y; av[6]=t1.z; av[7]=t1.w;
            if (wvalid) {
                const float* wv = Wg + (kt+1)*16;
                float4 u0 = *(const float4*)(wv + 0);
                float4 u1 = *(const float4*)(wv + 4);
                bv[0]=u0.x; bv[1]=u0.y; bv[2]=u0.z; bv[3]=u0.w;
                bv[4]=u1.x; bv[5]=u1.y; bv[6]=u1.z; bv[7]=u1.w;
            }
        }

        #pragma unroll
        for (int ks = 0; ks < 2; ks++) {
            const int kr = ks*8 + lt;
            float2 bf[4][2];
            #pragma unroll
            for (int j = 0; j < 4; j++) {
                int n0 = wn*32 + j*8 + lg;
                bf[j][0] = SB(buf, kr,   n0);
                bf[j][1] = SB(buf, kr+4, n0);
            }
            #pragma unroll
            for (int i = 0; i < 4; i++) {
                int m0 = wm*64 + i*16 + lg;
                float2 a0 = SA(buf, kr,   m0);
                float2 a1 = SA(buf, kr,   m0+8);
                float2 a2 = SA(buf, kr+4, m0);
                float2 a3 = SA(buf, kr+4, m0+8);
                uint32_t ah0 = __float_as_uint(a0.x), al0 = __float_as_uint(a0.y);
                uint32_t ah1 = __float_as_uint(a1.x), al1 = __float_as_uint(a1.y);
                uint32_t ah2 = __float_as_uint(a2.x), al2 = __float_as_uint(a2.y);
                uint32_t ah3 = __float_as_uint(a3.x), al3 = __float_as_uint(a3.y);
                #pragma unroll
                for (int j = 0; j < 4; j++) {
                    uint32_t bh0 = __float_as_uint(bf[j][0].x);
                    uint32_t bh1 = __float_as_uint(bf[j][1].x);
                    uint32_t bl0 = __float_as_uint(bf[j][0].y);
                    uint32_t bl1 = __float_as_uint(bf[j][1].y);
                    asm volatile(
                        "mma.sync.aligned.m16n8k8.row.col.f32.tf32.tf32.f32 "
                        "{%0,%1,%2,%3}, {%4,%5,%6,%7}, {%8,%9}, {%0,%1,%2,%3};"
                        : "+f"(acc[i][j][0]), "+f"(acc[i][j][1]),
                          "+f"(acc[i][j][2]), "+f"(acc[i][j][3])
                        : "r"(al0), "r"(al1), "r"(al2), "r"(al3),
                          "r"(bh0), "r"(bh1));
                    asm volatile(
                        "mma.sync.aligned.m16n8k8.row.col.f32.tf32.tf32.f32 "
                        "{%0,%1,%2,%3}, {%4,%5,%6,%7}, {%8,%9}, {%0,%1,%2,%3};"
                        : "+f"(acc[i][j][0]), "+f"(acc[i][j][1]),
                          "+f"(acc[i][j][2]), "+f"(acc[i][j][3])
                        : "r"(ah0), "r"(ah1), "r"(ah2), "r"(ah3),
                          "r"(bl0), "r"(bl1));
                    asm volatile(
                        "mma.sync.aligned.m16n8k8.row.col.f32.tf32.tf32.f32 "
                        "{%0,%1,%2,%3}, {%4,%5,%6,%7}, {%8,%9}, {%0,%1,%2,%3};"
                        : "+f"(acc[i][j][0]), "+f"(acc[i][j][1]),
                          "+f"(acc[i][j][2]), "+f"(acc[i][j][3])
                        : "r"(ah0), "r"(ah1), "r"(ah2), "r"(ah3),
                          "r"(bh0), "r"(bh1));
                }
            }
        }

        if (kt + 1 < KT) {
            const int nb = 1 - buf;
            #pragma unroll
            for (int q = 0; q < 8; q++) {
                float ah = f2tf32(av[q]);
                SA(nb, fh+q, fr) = make_float2(ah, f2tf32(av[q] - ah));
                float bh = f2tf32(bv[q]);
                SB(nb, fh+q, fr) = make_float2(bh, f2tf32(bv[q] - bh));
            }
        }
        __syncthreads();
    }

    #pragma unroll
    for (int i = 0; i < 4; i++) {
        int m = bm + wm*64 + i*16 + lg;
        #pragma unroll
        for (int j = 0; j < 4; j++) {
            int n = bn + wn*32 + j*8 + 2*lt;
            if (n < N) {
                *(float2*)&C[(size_t)m*ldC + n] =
                    make_float2(acc[i][j][0], acc[i][j][1]);
                *(float2*)&C[(size_t)(m+8)*ldC + n] =
                    make_float2(acc[i][j][2], acc[i][j][3]);
            }
        }
    }
}
#define MMA_SMEM (2*2*16*132*sizeof(float2))

// -------- fused: causal conv4+silu  AND  warp-dot dtprep (appended) ------
#define CONV_BLKS ((BL*CONVDIM + 255)/256)   // 32768
#define DT_BLKS   (BL/8)                     // 2048

__global__ __launch_bounds__(256)
void k_convdt(const float* __restrict__ conv_w, const float* __restrict__ conv_b,
              const float* __restrict__ dt_bias, const float* __restrict__ A_log,
              const float* __restrict__ in_w_layer) {
    if (blockIdx.x >= CONV_BLKS) {
        int bl   = (blockIdx.x - CONV_BLKS)*8 + ((int)threadIdx.x >> 5);
        int lane = threadIdx.x & 31;
        const float* xr = g_X + (size_t)bl*DMODEL;
        float x[6];
        #pragma unroll
        for (int r = 0; r < 6; r++) x[r] = xr[lane + 32*r];
        #pragma unroll
        for (int h = 0; h < NHEADS; h++) {
            const float* w = in_w_layer + (size_t)(896 + h)*DMODEL;
            float s = 0.f;
            #pragma unroll
            for (int r = 0; r < 6; r++) s = fmaf(x[r], w[lane + 32*r], s);
            #pragma unroll
            for (int o = 16; o > 0; o >>= 1)
                s += __shfl_xor_sync(0xffffffffu, s, o);
            if (lane == h) {
                float raw = s + dt_bias[h];
                float dt = (raw > 20.f) ? raw : log1pf(__expf(raw));
                float Ah = -__expf(A_log[h]);
                g_DTDEC[bl*16 + 2*h    ] = dt;
                g_DTDEC[bl*16 + 2*h + 1] = __expf(dt * Ah);
            }
        }
        return;
    }
    int idx = blockIdx.x*blockDim.x + threadIdx.x;
    int c  = idx & (CONVDIM-1);
    int bl = idx >> 9;
    int l  = bl & (SEQL-1);
    float acc = conv_b[c];
    const float* base = &g_ZX[(size_t)bl*DINPROJ + 384 + c];
    #pragma unroll
    for (int k = 0; k < 4; k++) {
        int ll = l - 3 + k;
        if (ll >= 0)
            acc = fmaf(base[(ptrdiff_t)(k-3)*DINPROJ], conv_w[c*4 + k], acc);
    }
    g_CONV[idx] = acc * sigf(acc);
}

// ================= block-cooperative chunked scan =========================
#define SCAN_SMEM (64*128*4 + 64*48*4 + 64*8)   // 45568 B

__global__ __launch_bounds__(384, 4)
void k_scan_blk(const float* __restrict__ Dvec) {
    extern __shared__ float sm[];
    float*  sBC  = sm;                 // [64][128]
    float*  sX   = sBC + 64*128;       // [64][48]
    float2* sdde = (float2*)(sX + 64*48);  // [64]

    int ck = blockIdx.x & (NCHUNK-1);
    int bh = blockIdx.x >> 6;
    int h  = bh & 7, b = bh >> 3;
    int bl0 = b*SEQL + ck*CHUNKL;
    int tid  = threadIdx.x;
    int lane = tid & 31;
    int wid  = tid >> 5;
    int p0   = wid*4;

    const float* convb = g_CONV + (size_t)bl0*CONVDIM;

    for (int q = tid; q < 64*32; q += 384) {
        int t = q >> 5, c4 = (q & 31) << 2;
        *(float4*)&sBC[t*128 + c4] =
            *(const float4*)&convb[(size_t)t*CONVDIM + 384 + c4];
    }
    for (int q = tid; q < 64*12; q += 384) {
        int t = q / 12, c4 = (q % 12) << 2;
        *(float4*)&sX[t*48 + c4] =
            *(const float4*)&convb[(size_t)t*CONVDIM + h*HEADDIM + c4];
    }
    if (tid < 64)
        sdde[tid] = *(const float2*)&g_DTDEC[(size_t)(bl0 + tid)*16 + 2*h];
    __syncthreads();

    if (tid == 0) {
        float pr = 1.f;
        for (int t = 0; t < CHUNKL; t++) {
            pr *= sdde[t].y;
            g_LAM[(size_t)(bl0 + t)*NHEADS + h] = pr;
        }
        g_P[bh*NCHUNK + ck] = pr;
    }

    const float Dh = Dvec[h];
    const int g    = lane >> 3;
    const int poff = (g >> 1) | ((g & 1) << 1);
    const bool st  = (lane & 7) == 0;
    float* yo = g_Y + (size_t)bl0*DINNER + h*HEADDIM + p0 + poff;

    float h0[4], h1[4];
    #pragma unroll
    for (int i = 0; i < 4; i++) { h0[i] = 0.f; h1[i] = 0.f; }

    #pragma unroll 2
    for (int t = 0; t < CHUNKL; t++) {
        float2 dde = sdde[t];
        float4 xv  = *(const float4*)&sX[t*48 + p0];
        float2 Bv  = *(const float2*)&sBC[t*128 + 2*lane];
        float2 Cv  = *(const float2*)&sBC[t*128 + 64 + 2*lane];
        float bx = dde.x * Bv.x;
        float by = dde.x * Bv.y;
        float xa[4] = {xv.x, xv.y, xv.z, xv.w};
        float y[4];
        #pragma unroll
        for (int i = 0; i < 4; i++) {
            h0[i] = fmaf(h0[i], dde.y, xa[i]*bx);
            h1[i] = fmaf(h1[i], dde.y, xa[i]*by);
            y[i]  = fmaf(h0[i], Cv.x, h1[i]*Cv.y);
        }
        #pragma unroll
        for (int i = 0; i < 4; i++)
            y[i] += __shfl_xor_sync(0xffffffffu, y[i], 16);
        float za = (lane & 16) ? y[1] : y[0];
        float zb = (lane & 16) ? y[3] : y[2];
        za += __shfl_xor_sync(0xffffffffu, za, 8);
        zb += __shfl_xor_sync(0xffffffffu, zb, 8);
        float wv = (lane & 8) ? zb : za;
        wv += __shfl_xor_sync(0xffffffffu, wv, 4);
        wv += __shfl_xor_sync(0xffffffffu, wv, 2);
        wv += __shfl_xor_sync(0xffffffffu, wv, 1);
        if (st) {
            float xs = (g == 0) ? xa[0] : (g == 1) ? xa[2]
                     : (g == 2) ? xa[1] : xa[3];
            *yo = fmaf(Dh, xs, wv);
        }
        yo += DINNER;
    }

    float* S = &g_S[((((size_t)bh*NCHUNK + ck)*HEADDIM) + p0)*DSTATE + 2*lane];
    #pragma unroll
    for (int i = 0; i < 4; i++)
        *(float2*)(S + (size_t)i*DSTATE) = make_float2(h0[i], h1[i]);
}

// inter-chunk recurrence — register-staged
__global__ __launch_bounds__(256)
void k_chunk_seq() {
    int idx = blockIdx.x*blockDim.x + threadIdx.x;
    if (idx >= BATCHN*NHEADS*HEADDIM*DSTATE) return;
    int pn = idx % (HEADDIM*DSTATE);
    int bh = idx / (HEADDIM*DSTATE);
    const float* P = g_P + bh*NCHUNK;
    float* S = g_S + (size_t)bh*NCHUNK*HEADDIM*DSTATE + pn;

    float v[NCHUNK];
    #pragma unroll
    for (int k = 0; k < NCHUNK; k++)
        v[k] = __ldg(S + (size_t)k*HEADDIM*DSTATE);

    float h = 0.f;
    #pragma unroll
    for (int k = 0; k < NCHUNK; k++) {
        float s = v[k];
        v[k] = h;
        h = fmaf(h, P[k], s);
    }

    #pragma unroll
    for (int k = 0; k < NCHUNK; k++)
        S[(size_t)k*HEADDIM*DSTATE] = v[k];
}

// correction: Y[t][p] += Lam_t * sum_n C[t][n] * Hinit[p][n]
__global__ __launch_bounds__(256)
void k_corr() {
    __shared__ float Cs[64][68];
    __shared__ float Hs[64][49];
    __shared__ float Ls[64];

    int ck = blockIdx.x % NCHUNK;
    int bh = blockIdx.x / NCHUNK;
    int h  = bh & 7, b = bh >> 3;
    int bl0 = b*SEQL + ck*CHUNKL;
    int tid = threadIdx.x;

    #pragma unroll
    for (int q = tid; q < 64*16; q += 256) {
        int t  = q >> 4;
        int n4 = (q & 15) << 2;
        float4 v = *(const float4*)&g_CONV[(size_t)(bl0 + t)*CONVDIM + 448 + n4];
        Cs[n4+0][t] = v.x; Cs[n4+1][t] = v.y;
        Cs[n4+2][t] = v.z; Cs[n4+3][t] = v.w;
    }
    const float* Sb = g_S + (((size_t)bh*NCHUNK + ck)*HEADDIM)*DSTATE;
    #pragma unroll
    for (int q = tid; q < 48*16; q += 256) {
        int p  = q >> 4;
        int n4 = (q & 15) << 2;
        float4 v = *(const float4*)&Sb[(size_t)p*DSTATE + n4];
        Hs[n4+0][p] = v.x; Hs[n4+1][p] = v.y;
        Hs[n4+2][p] = v.z; Hs[n4+3][p] = v.w;
    }
    if (tid < 64)
        Ls[tid] = g_LAM[(size_t)(bl0 + tid)*NHEADS + h];
    __syncthreads();

    int tx = tid & 15, ty = tid >> 4;
    int pp = tx*3, tt = ty*4;

    float acc[4][3];
    #pragma unroll
    for (int i = 0; i < 4; i++)
        #pragma unroll
        for (int j = 0; j < 3; j++) acc[i][j] = 0.f;

    #pragma unroll 4
    for (int n = 0; n < 64; n++) {
        float4 c = *(const float4*)&Cs[n][tt];
        float ca[4] = {c.x, c.y, c.z, c.w};
        float hh0 = Hs[n][pp], hh1 = Hs[n][pp+1], hh2 = Hs[n][pp+2];
        #pragma unroll
        for (int i = 0; i < 4; i++) {
            acc[i][0] = fmaf(ca[i], hh0, acc[i][0]);
            acc[i][1] = fmaf(ca[i], hh1, acc[i][1]);
            acc[i][2] = fmaf(ca[i], hh2, acc[i][2]);
        }
    }

    #pragma unroll
    for (int i = 0; i < 4; i++) {
        float lam = Ls[tt + i];
        float* yr = g_Y + (size_t)(bl0 + tt + i)*DINNER + h*HEADDIM + pp;
        #pragma unroll
        for (int j = 0; j < 3; j++)
            yr[j] = fmaf(lam, acc[i][j], yr[j]);
    }
}

// ---------------- gated RMSNorm ------------------------------------------
__global__ __launch_bounds__(128)
void k_gated_rms(const float* __restrict__ norm_w) {
    int bl = blockIdx.x;
    int t  = threadIdx.x;
    int lane = t & 31, wid = t >> 5;
    __shared__ float sh[4];
    float v[3];
    float ss = 0.f;
    #pragma unroll
    for (int j = 0; j < 3; j++) {
        int d = t + j*128;
        float y = g_Y[(size_t)bl*DINNER + d];
        float z = g_ZX[(size_t)bl*DINPROJ + d];
        y *= z * sigf(z);
        v[j] = y;
        ss = fmaf(y, y, ss);
    }
    #pragma unroll
    for (int o = 16; o > 0; o >>= 1) ss += __shfl_xor_sync(0xffffffffu, ss, o);
    if (lane == 0) sh[wid] = ss;
    __syncthreads();
    ss = sh[0] + sh[1] + sh[2] + sh[3];
    float rms = rsqrtf(ss * (1.f/DINNER) + 1e-5f);
    #pragma unroll
    for (int j = 0; j < 3; j++) {
        int d = t + j*128;
        g_Y[(size_t)bl*DINNER + d] = v[j] * rms * norm_w[d];
    }
}

// ---------------- residual add + layernorm -> X --------------------------
__global__ __launch_bounds__(192)
void k_res_ln(const float* __restrict__ ln_w, const float* __restrict__ ln_b) {
    int bl = blockIdx.x;
    int d  = threadIdx.x;
    int lane = d & 31, wid = d >> 5;
    __shared__ float shs[6], shq[6];
    float x = g_O[(size_t)bl*DMODEL + d] + g_X[(size_t)bl*DMODEL + d];
    float s = x, q = x*x;
    #pragma unroll
    for (int o = 16; o > 0; o >>= 1) {
        s += __shfl_xor_sync(0xffffffffu, s, o);
        q += __shfl_xor_sync(0xffffffffu, q, o);
    }
    if (lane == 0) { shs[wid] = s; shq[wid] = q; }
    __syncthreads();
    s = 0.f; q = 0.f;
    #pragma unroll
    for (int i = 0; i < 6; i++) { s += shs[i]; q += shq[i]; }
    float mu  = s * (1.f/DMODEL);
    float var = q * (1.f/DMODEL) - mu*mu;
    g_X[(size_t)bl*DMODEL + d] = (x - mu) * rsqrtf(var + 1e-5f) * ln_w[d] + ln_b[d];
}

// ---------------- output linear ------------------------------------------
__global__ __launch_bounds__(192)
void k_final(const float* __restrict__ w, const float* __restrict__ bias,
             float* __restrict__ out) {
    int bl = blockIdx.x;
    int d  = threadIdx.x;
    int lane = d & 31, wid = d >> 5;
    int b = bl / SEQL, l = bl % SEQL;
    __shared__ float sh[6][4];
    float x = g_X[(size_t)bl*DMODEL + d];
    float p0 = x * w[0*DMODEL + d];
    float p1 = x * w[1*DMODEL + d];
    float p2 = x * w[2*DMODEL + d];
    float p3 = x * w[3*DMODEL + d];
    #pragma unroll
    for (int o = 16; o > 0; o >>= 1) {
        p0 += __shfl_xor_sync(0xffffffffu, p0, o);
        p1 += __shfl_xor_sync(0xffffffffu, p1, o);
        p2 += __shfl_xor_sync(0xffffffffu, p2, o);
        p3 += __shfl_xor_sync(0xffffffffu, p3, o);
    }
    if (lane == 0) { sh[wid][0]=p0; sh[wid][1]=p1; sh[wid][2]=p2; sh[wid][3]=p3; }
    __syncthreads();
    if (d < 4) {
        float s = 0.f;
        #pragma unroll
        for (int i = 0; i < 6; i++) s += sh[i][d];
        out[(size_t)b*4*SEQL + (size_t)d*SEQL + l] = s + bias[d];
    }
}

// ---------------- driver --------------------------------------------------
extern "C" void kernel_launch(void* const* d_in, const int* in_sizes, int n_in,
                              void* d_out, int out_size) {
    const float* inp      = (const float*)d_in[0];
    const float* lin_in_w = (const float*)d_in[1];
    const float* lin_in_b = (const float*)d_in[2];
    const float* in_w     = (const float*)d_in[3];
    const float* conv_w   = (const float*)d_in[4];
    const float* conv_b   = (const float*)d_in[5];
    const float* dt_bias  = (const float*)d_in[6];
    const float* A_log    = (const float*)d_in[7];
    const float* Dv       = (const float*)d_in[8];
    const float* norm_w   = (const float*)d_in[9];
    const float* out_w    = (const float*)d_in[10];
    const float* ln_w     = (const float*)d_in[11];
    const float* ln_b     = (const float*)d_in[12];
    const float* lo_w     = (const float*)d_in[13];
    const float* lo_b     = (const float*)d_in[14];
    float* out = (float*)d_out;

    static cudaStream_t s2 = nullptr;
    static cudaEvent_t evA = nullptr, evC = nullptr;
    if (!s2) {
        cudaStreamCreateWithFlags(&s2, cudaStreamNonBlocking);
        cudaEventCreateWithFlags(&evA, cudaEventDisableTiming);
        cudaEventCreateWithFlags(&evC, cudaEventDisableTiming);
        cudaFuncSetAttribute(k_mma, cudaFuncAttributeMaxDynamicSharedMemorySize,
                             (int)MMA_SMEM);
        cudaFuncSetAttribute(k_scan_blk, cudaFuncAttributeMaxDynamicSharedMemorySize,
                             (int)SCAN_SMEM);
    }

    const int scan_blocks = BATCHN*NHEADS*NCHUNK;   // 2048
    const int corr_blocks = BATCHN*NHEADS*NCHUNK;

    k_lin_in<<<(BL*DMODEL + 255)/256, 256>>>(inp, lin_in_w, lin_in_b);

    for (int layer = 0; layer < NLAYERS; layer++) {
        const float* in_w_l = in_w + (size_t)layer*DINPROJ*DMODEL;

        // in_proj A: xBC columns [384, 896) -> N=512 (4 exact tiles), cofs=384
        k_mma<<<4*(BL/128), 256, MMA_SMEM>>>(
            in_w_l + (size_t)384*DMODEL, 0, 512, DMODEL, DINPROJ, 384);
        cudaEventRecord(evA, 0);

        // in_proj B: z columns [0, 384) on stream 0 (overlaps s2 chain)
        k_mma<<<3*(BL/128), 256, MMA_SMEM>>>(
            in_w_l, 0, 384, DMODEL, DINPROJ, 0);

        // s2 chain: conv + warp-dot dtprep -> scan -> chunk_seq -> corr
        cudaStreamWaitEvent(s2, evA, 0);
        k_convdt<<<CONV_BLKS + DT_BLKS, 256, 0, s2>>>(
            conv_w + (size_t)layer*CONVDIM*4,
            conv_b + (size_t)layer*CONVDIM,
            dt_bias + layer*NHEADS,
            A_log + layer*NHEADS,
            in_w_l);
        k_scan_blk<<<scan_blocks, 384, SCAN_SMEM, s2>>>(Dv + layer*NHEADS);
        k_chunk_seq<<<(BATCHN*NHEADS*HEADDIM*DSTATE + 255)/256, 256, 0, s2>>>();
        k_corr<<<corr_blocks, 256, 0, s2>>>();
        cudaEventRecord(evC, s2);

        // join; gated RMS needs z (stream 0) + corrected Y (s2)
        cudaStreamWaitEvent(0, evC, 0);
        k_gated_rms<<<BL, 128>>>(norm_w + (size_t)layer*DINNER);
        k_mma<<<2*(BL/128), 256, MMA_SMEM>>>(
            out_w + (size_t)layer*DMODEL*DINNER, 1, DMODEL, DINNER, DMODEL, 0);
        k_res_ln<<<BL, 192>>>(ln_w + (size_t)layer*DMODEL,
                              ln_b + (size_t)layer*DMODEL);
    }

    k_final<<<BL, 192>>>(lo_w, lo_b, out);
}

// round 17
// speedup vs baseline: 1.0632x; 1.0513x over previous
#include <cuda_runtime.h>
#include <math.h>
#include <stdint.h>

#define SEQL    4096
#define BATCHN  4
#define BL      (BATCHN*SEQL)       // 16384
#define DMODEL  192
#define DINNER  384
#define DSTATE  64
#define NHEADS  8
#define HEADDIM 48
#define CONVDIM 512
#define DINPROJ 904
#define NLAYERS 8
#define NCHUNK  64
#define CHUNKL  64
#define BCW     128                 // B|C conv buffer row width

// ---------------- scratch (device globals) -------------------------------
__device__ float g_X[BL*DMODEL];
__device__ float g_ZX[BL*DINPROJ];
__device__ float g_CONV[BL*BCW];        // conv'd B|C only
__device__ float g_DTDEC[BL*NHEADS*2];
__device__ float g_Y[BL*DINNER];
__device__ float g_O[BL*DMODEL];
__device__ float g_S[BATCHN*NHEADS*NCHUNK*HEADDIM*DSTATE];
__device__ float g_P[BATCHN*NHEADS*NCHUNK];
__device__ float g_LAM[BL*NHEADS];

__device__ __forceinline__ float sigf(float x){ return 1.f/(1.f+__expf(-x)); }

__device__ __forceinline__ float f2tf32(float x) {
    uint32_t o;
    asm("cvt.rna.tf32.f32 %0, %1;" : "=r"(o) : "f"(x));
    return __uint_as_float(o);
}

// ---------------- input linear -------------------------------------------
__global__ void k_lin_in(const float* __restrict__ inp,
                         const float* __restrict__ w,
                         const float* __restrict__ bias) {
    int idx = blockIdx.x*blockDim.x + threadIdx.x;
    if (idx >= BL*DMODEL) return;
    int d  = idx % DMODEL;
    int bl = idx / DMODEL;
    int b = bl / SEQL, l = bl % SEQL;
    const float* ip = inp + (size_t)b*3*SEQL + l;
    float acc = bias[d];
    acc = fmaf(ip[0],      w[d*3+0], acc);
    acc = fmaf(ip[SEQL],   w[d*3+1], acc);
    acc = fmaf(ip[2*SEQL], w[d*3+2], acc);
    g_X[idx] = fmaxf(acc, 0.f);
}

// ---------------- 3xTF32 GEMM, double-buffered, hi/lo packed -------------
#define SA(b,k,m) sA[(((b)*16+(k))*132)+(m)]
#define SB(b,k,m) sB[(((b)*16+(k))*132)+(m)]

__global__ __launch_bounds__(256, 2)
void k_mma(const float* __restrict__ W, int mode, int N, int K, int ldC) {
    const float* A;
    float* C;
    if (mode == 0) { A = g_X; C = g_ZX; } else { A = g_Y; C = g_O; }

    extern __shared__ float2 smem[];
    float2* sA = smem;
    float2* sB = smem + 2*16*132;

    const int nbx = (N + 127)/128;
    const int bm = (blockIdx.x / nbx) * 128;
    const int bn = (blockIdx.x % nbx) * 128;
    const int tid  = threadIdx.x;
    const int lane = tid & 31;
    const int wid  = tid >> 5;
    const int wm = wid >> 2;
    const int wn = wid & 3;
    const int lg = lane >> 2;
    const int lt = lane & 3;

    float acc[4][4][4];
    #pragma unroll
    for (int i = 0; i < 4; i++)
        #pragma unroll
        for (int j = 0; j < 4; j++)
            #pragma unroll
            for (int r = 0; r < 4; r++) acc[i][j][r] = 0.f;

    const int fr = tid >> 1;
    const int fh = (tid & 1) * 8;
    const bool wvalid = (bn + fr) < N;
    const float* Ag = A + (size_t)(bm + fr)*K + fh;
    const float* Wg = wvalid ? (W + (size_t)(bn + fr)*K + fh) : W;

    float av[8], bv[8];
    const int KT = K / 16;

    {
        float4 t0 = *(const float4*)(Ag + 0);
        float4 t1 = *(const float4*)(Ag + 4);
        av[0]=t0.x; av[1]=t0.y; av[2]=t0.z; av[3]=t0.w;
        av[4]=t1.x; av[5]=t1.y; av[6]=t1.z; av[7]=t1.w;
        if (wvalid) {
            float4 u0 = *(const float4*)(Wg + 0);
            float4 u1 = *(const float4*)(Wg + 4);
            bv[0]=u0.x; bv[1]=u0.y; bv[2]=u0.z; bv[3]=u0.w;
            bv[4]=u1.x; bv[5]=u1.y; bv[6]=u1.z; bv[7]=u1.w;
        } else {
            #pragma unroll
            for (int q = 0; q < 8; q++) bv[q] = 0.f;
        }
    }
    #pragma unroll
    for (int q = 0; q < 8; q++) {
        float ah = f2tf32(av[q]);
        SA(0, fh+q, fr) = make_float2(ah, f2tf32(av[q] - ah));
        float bh = f2tf32(bv[q]);
        SB(0, fh+q, fr) = make_float2(bh, f2tf32(bv[q] - bh));
    }
    __syncthreads();

    for (int kt = 0; kt < KT; kt++) {
        const int buf = kt & 1;
        if (kt + 1 < KT) {
            const float* an = Ag + (kt+1)*16;
            float4 t0 = *(const float4*)(an + 0);
            float4 t1 = *(const float4*)(an + 4);
            av[0]=t0.x; av[1]=t0.y; av[2]=t0.z; av[3]=t0.w;
            av[4]=t1.x; av[5]=t1.y; av[6]=t1.z; av[7]=t1.w;
            if (wvalid) {
                const float* wv = Wg + (kt+1)*16;
                float4 u0 = *(const float4*)(wv + 0);
                float4 u1 = *(const float4*)(wv + 4);
                bv[0]=u0.x; bv[1]=u0.y; bv[2]=u0.z; bv[3]=u0.w;
                bv[4]=u1.x; bv[5]=u1.y; bv[6]=u1.z; bv[7]=u1.w;
            }
        }

        #pragma unroll
        for (int ks = 0; ks < 2; ks++) {
            const int kr = ks*8 + lt;
            float2 bf[4][2];
            #pragma unroll
            for (int j = 0; j < 4; j++) {
                int n0 = wn*32 + j*8 + lg;
                bf[j][0] = SB(buf, kr,   n0);
                bf[j][1] = SB(buf, kr+4, n0);
            }
            #pragma unroll
            for (int i = 0; i < 4; i++) {
                int m0 = wm*64 + i*16 + lg;
                float2 a0 = SA(buf, kr,   m0);
                float2 a1 = SA(buf, kr,   m0+8);
                float2 a2 = SA(buf, kr+4, m0);
                float2 a3 = SA(buf, kr+4, m0+8);
                uint32_t ah0 = __float_as_uint(a0.x), al0 = __float_as_uint(a0.y);
                uint32_t ah1 = __float_as_uint(a1.x), al1 = __float_as_uint(a1.y);
                uint32_t ah2 = __float_as_uint(a2.x), al2 = __float_as_uint(a2.y);
                uint32_t ah3 = __float_as_uint(a3.x), al3 = __float_as_uint(a3.y);
                #pragma unroll
                for (int j = 0; j < 4; j++) {
                    uint32_t bh0 = __float_as_uint(bf[j][0].x);
                    uint32_t bh1 = __float_as_uint(bf[j][1].x);
                    uint32_t bl0 = __float_as_uint(bf[j][0].y);
                    uint32_t bl1 = __float_as_uint(bf[j][1].y);
                    asm volatile(
                        "mma.sync.aligned.m16n8k8.row.col.f32.tf32.tf32.f32 "
                        "{%0,%1,%2,%3}, {%4,%5,%6,%7}, {%8,%9}, {%0,%1,%2,%3};"
                        : "+f"(acc[i][j][0]), "+f"(acc[i][j][1]),
                          "+f"(acc[i][j][2]), "+f"(acc[i][j][3])
                        : "r"(al0), "r"(al1), "r"(al2), "r"(al3),
                          "r"(bh0), "r"(bh1));
                    asm volatile(
                        "mma.sync.aligned.m16n8k8.row.col.f32.tf32.tf32.f32 "
                        "{%0,%1,%2,%3}, {%4,%5,%6,%7}, {%8,%9}, {%0,%1,%2,%3};"
                        : "+f"(acc[i][j][0]), "+f"(acc[i][j][1]),
                          "+f"(acc[i][j][2]), "+f"(acc[i][j][3])
                        : "r"(ah0), "r"(ah1), "r"(ah2), "r"(ah3),
                          "r"(bl0), "r"(bl1));
                    asm volatile(
                        "mma.sync.aligned.m16n8k8.row.col.f32.tf32.tf32.f32 "
                        "{%0,%1,%2,%3}, {%4,%5,%6,%7}, {%8,%9}, {%0,%1,%2,%3};"
                        : "+f"(acc[i][j][0]), "+f"(acc[i][j][1]),
                          "+f"(acc[i][j][2]), "+f"(acc[i][j][3])
                        : "r"(ah0), "r"(ah1), "r"(ah2), "r"(ah3),
                          "r"(bh0), "r"(bh1));
                }
            }
        }

        if (kt + 1 < KT) {
            const int nb = 1 - buf;
            #pragma unroll
            for (int q = 0; q < 8; q++) {
                float ah = f2tf32(av[q]);
                SA(nb, fh+q, fr) = make_float2(ah, f2tf32(av[q] - ah));
                float bh = f2tf32(bv[q]);
                SB(nb, fh+q, fr) = make_float2(bh, f2tf32(bv[q] - bh));
            }
        }
        __syncthreads();
    }

    #pragma unroll
    for (int i = 0; i < 4; i++) {
        int m = bm + wm*64 + i*16 + lg;
        #pragma unroll
        for (int j = 0; j < 4; j++) {
            int n = bn + wn*32 + j*8 + 2*lt;
            if (n < N) {
                *(float2*)&C[(size_t)m*ldC + n] =
                    make_float2(acc[i][j][0], acc[i][j][1]);
                *(float2*)&C[(size_t)(m+8)*ldC + n] =
                    make_float2(acc[i][j][2], acc[i][j][3]);
            }
        }
    }
}
#define MMA_SMEM (2*2*16*132*sizeof(float2))

// -------- fused: B/C conv4+silu (compact out)  AND  warp-dot dtprep ------
#define CONV_BLKS ((BL*BCW + 255)/256)       // 8192
#define DT_BLKS   (BL/8)                     // 2048

__global__ __launch_bounds__(256)
void k_convdt(const float* __restrict__ conv_w, const float* __restrict__ conv_b,
              const float* __restrict__ dt_bias, const float* __restrict__ A_log,
              const float* __restrict__ in_w_layer) {
    if (blockIdx.x >= CONV_BLKS) {
        int bl   = (blockIdx.x - CONV_BLKS)*8 + ((int)threadIdx.x >> 5);
        int lane = threadIdx.x & 31;
        const float* xr = g_X + (size_t)bl*DMODEL;
        float x[6];
        #pragma unroll
        for (int r = 0; r < 6; r++) x[r] = xr[lane + 32*r];
        #pragma unroll
        for (int h = 0; h < NHEADS; h++) {
            const float* w = in_w_layer + (size_t)(896 + h)*DMODEL;
            float s = 0.f;
            #pragma unroll
            for (int r = 0; r < 6; r++) s = fmaf(x[r], w[lane + 32*r], s);
            #pragma unroll
            for (int o = 16; o > 0; o >>= 1)
                s += __shfl_xor_sync(0xffffffffu, s, o);
            if (lane == h) {
                float raw = s + dt_bias[h];
                float dt = (raw > 20.f) ? raw : log1pf(__expf(raw));
                float Ah = -__expf(A_log[h]);
                g_DTDEC[bl*16 + 2*h    ] = dt;
                g_DTDEC[bl*16 + 2*h + 1] = __expf(dt * Ah);
            }
        }
        return;
    }
    // B/C conv path: compact 128-wide output
    int idx = blockIdx.x*blockDim.x + threadIdx.x;
    int c  = idx & (BCW-1);          // 0..127
    int bl = idx >> 7;
    int l  = bl & (SEQL-1);
    int col = 384 + c;               // column in xBC space
    float acc = conv_b[col];
    const float* base = &g_ZX[(size_t)bl*DINPROJ + 384 + col];  // note: +384 z offset
    #pragma unroll
    for (int k = 0; k < 4; k++) {
        int ll = l - 3 + k;
        if (ll >= 0)
            acc = fmaf(g_ZX[((size_t)bl + (k-3))*DINPROJ + 384 + col - 384 + 384],
                       0.f, acc);   // placeholder (replaced below)
    }
    // recompute cleanly (compiler folds): raw xBC value at row bl+(k-3), col
    acc = conv_b[col];
    const float* zx = &g_ZX[(size_t)bl*DINPROJ + 384 + c + 384];
    (void)base; (void)zx;
    const float* raw = &g_ZX[(size_t)bl*DINPROJ + 384 + c + 0];
    // xBC block starts at column 384 in g_ZX; B/C start at 384+384=768
    const float* rawbc = &g_ZX[(size_t)bl*DINPROJ + 768 + c];
    #pragma unroll
    for (int k = 0; k < 4; k++) {
        int ll = l - 3 + k;
        if (ll >= 0)
            acc = fmaf(rawbc[(ptrdiff_t)(k-3)*DINPROJ], conv_w[col*4 + k], acc);
    }
    (void)raw;
    g_CONV[(size_t)bl*BCW + c] = acc * sigf(acc);
}

// ================= block-cooperative chunked scan =========================
// stages B/C from compact g_CONV; computes x-conv+silu in staging (disjoint
// per head -> no duplication).
#define SCAN_SMEM (64*128*4 + 64*48*4 + 64*8)   // 45568 B

__global__ __launch_bounds__(384, 4)
void k_scan_blk(const float* __restrict__ Dvec,
                const float* __restrict__ conv_w,
                const float* __restrict__ conv_b) {
    extern __shared__ float sm[];
    float*  sBC  = sm;                 // [64][128]
    float*  sX   = sBC + 64*128;       // [64][48]
    float2* sdde = (float2*)(sX + 64*48);  // [64]

    int ck = blockIdx.x & (NCHUNK-1);
    int bh = blockIdx.x >> 6;
    int h  = bh & 7, b = bh >> 3;
    int bl0 = b*SEQL + ck*CHUNKL;
    int tid  = threadIdx.x;
    int lane = tid & 31;
    int wid  = tid >> 5;
    int p0   = wid*4;

    // stage B/C from compact buffer (coalesced: rows are 512B)
    const float* convb = g_CONV + (size_t)bl0*BCW;
    for (int q = tid; q < 64*32; q += 384) {
        int t = q >> 5, c4 = (q & 31) << 2;
        *(float4*)&sBC[t*128 + c4] = *(const float4*)&convb[t*BCW + c4];
    }
    // stage x: conv4+silu computed from raw g_ZX (this head's 48 cols)
    for (int q = tid; q < 64*48; q += 384) {
        int t = q / 48, c = q % 48;
        int col = h*HEADDIM + c;                 // x column in xBC space
        float acc = conv_b[col];
        const float* zx = &g_ZX[(size_t)(bl0 + t)*DINPROJ + 384 + col];
        #pragma unroll
        for (int k = 0; k < 4; k++) {
            int tt = t - 3 + k;
            if (ck > 0 || tt >= 0)
                acc = fmaf(zx[(ptrdiff_t)(k-3)*DINPROJ], conv_w[col*4 + k], acc);
        }
        sX[t*48 + c] = acc * sigf(acc);
    }
    if (tid < 64)
        sdde[tid] = *(const float2*)&g_DTDEC[(size_t)(bl0 + tid)*16 + 2*h];
    __syncthreads();

    if (tid == 0) {
        float pr = 1.f;
        for (int t = 0; t < CHUNKL; t++) {
            pr *= sdde[t].y;
            g_LAM[(size_t)(bl0 + t)*NHEADS + h] = pr;
        }
        g_P[bh*NCHUNK + ck] = pr;
    }

    const float Dh = Dvec[h];
    const int g    = lane >> 3;
    const int poff = (g >> 1) | ((g & 1) << 1);
    const bool st  = (lane & 7) == 0;
    float* yo = g_Y + (size_t)bl0*DINNER + h*HEADDIM + p0 + poff;

    float h0[4], h1[4];
    #pragma unroll
    for (int i = 0; i < 4; i++) { h0[i] = 0.f; h1[i] = 0.f; }

    #pragma unroll 2
    for (int t = 0; t < CHUNKL; t++) {
        float2 dde = sdde[t];
        float4 xv  = *(const float4*)&sX[t*48 + p0];
        float2 Bv  = *(const float2*)&sBC[t*128 + 2*lane];
        float2 Cv  = *(const float2*)&sBC[t*128 + 64 + 2*lane];
        float bx = dde.x * Bv.x;
        float by = dde.x * Bv.y;
        float xa[4] = {xv.x, xv.y, xv.z, xv.w};
        float y[4];
        #pragma unroll
        for (int i = 0; i < 4; i++) {
            h0[i] = fmaf(h0[i], dde.y, xa[i]*bx);
            h1[i] = fmaf(h1[i], dde.y, xa[i]*by);
            y[i]  = fmaf(h0[i], Cv.x, h1[i]*Cv.y);
        }
        #pragma unroll
        for (int i = 0; i < 4; i++)
            y[i] += __shfl_xor_sync(0xffffffffu, y[i], 16);
        float za = (lane & 16) ? y[1] : y[0];
        float zb = (lane & 16) ? y[3] : y[2];
        za += __shfl_xor_sync(0xffffffffu, za, 8);
        zb += __shfl_xor_sync(0xffffffffu, zb, 8);
        float wv = (lane & 8) ? zb : za;
        wv += __shfl_xor_sync(0xffffffffu, wv, 4);
        wv += __shfl_xor_sync(0xffffffffu, wv, 2);
        wv += __shfl_xor_sync(0xffffffffu, wv, 1);
        if (st) {
            float xs = (g == 0) ? xa[0] : (g == 1) ? xa[2]
                     : (g == 2) ? xa[1] : xa[3];
            *yo = fmaf(Dh, xs, wv);
        }
        yo += DINNER;
    }

    float* S = &g_S[((((size_t)bh*NCHUNK + ck)*HEADDIM) + p0)*DSTATE + 2*lane];
    #pragma unroll
    for (int i = 0; i < 4; i++)
        *(float2*)(S + (size_t)i*DSTATE) = make_float2(h0[i], h1[i]);
}

// inter-chunk recurrence — register-staged
__global__ __launch_bounds__(256)
void k_chunk_seq() {
    int idx = blockIdx.x*blockDim.x + threadIdx.x;
    if (idx >= BATCHN*NHEADS*HEADDIM*DSTATE) return;
    int pn = idx % (HEADDIM*DSTATE);
    int bh = idx / (HEADDIM*DSTATE);
    const float* P = g_P + bh*NCHUNK;
    float* S = g_S + (size_t)bh*NCHUNK*HEADDIM*DSTATE + pn;

    float v[NCHUNK];
    #pragma unroll
    for (int k = 0; k < NCHUNK; k++)
        v[k] = __ldg(S + (size_t)k*HEADDIM*DSTATE);

    float h = 0.f;
    #pragma unroll
    for (int k = 0; k < NCHUNK; k++) {
        float s = v[k];
        v[k] = h;
        h = fmaf(h, P[k], s);
    }

    #pragma unroll
    for (int k = 0; k < NCHUNK; k++)
        S[(size_t)k*HEADDIM*DSTATE] = v[k];
}

// correction: Y[t][p] += Lam_t * sum_n C[t][n] * Hinit[p][n]
__global__ __launch_bounds__(256)
void k_corr() {
    __shared__ float Cs[64][68];
    __shared__ float Hs[64][49];
    __shared__ float Ls[64];

    int ck = blockIdx.x % NCHUNK;
    int bh = blockIdx.x / NCHUNK;
    int h  = bh & 7, b = bh >> 3;
    int bl0 = b*SEQL + ck*CHUNKL;
    int tid = threadIdx.x;

    #pragma unroll
    for (int q = tid; q < 64*16; q += 256) {
        int t  = q >> 4;
        int n4 = (q & 15) << 2;
        float4 v = *(const float4*)&g_CONV[(size_t)(bl0 + t)*BCW + 64 + n4];
        Cs[n4+0][t] = v.x; Cs[n4+1][t] = v.y;
        Cs[n4+2][t] = v.z; Cs[n4+3][t] = v.w;
    }
    const float* Sb = g_S + (((size_t)bh*NCHUNK + ck)*HEADDIM)*DSTATE;
    #pragma unroll
    for (int q = tid; q < 48*16; q += 256) {
        int p  = q >> 4;
        int n4 = (q & 15) << 2;
        float4 v = *(const float4*)&Sb[(size_t)p*DSTATE + n4];
        Hs[n4+0][p] = v.x; Hs[n4+1][p] = v.y;
        Hs[n4+2][p] = v.z; Hs[n4+3][p] = v.w;
    }
    if (tid < 64)
        Ls[tid] = g_LAM[(size_t)(bl0 + tid)*NHEADS + h];
    __syncthreads();

    int tx = tid & 15, ty = tid >> 4;
    int pp = tx*3, tt = ty*4;

    float acc[4][3];
    #pragma unroll
    for (int i = 0; i < 4; i++)
        #pragma unroll
        for (int j = 0; j < 3; j++) acc[i][j] = 0.f;

    #pragma unroll 4
    for (int n = 0; n < 64; n++) {
        float4 c = *(const float4*)&Cs[n][tt];
        float ca[4] = {c.x, c.y, c.z, c.w};
        float hh0 = Hs[n][pp], hh1 = Hs[n][pp+1], hh2 = Hs[n][pp+2];
        #pragma unroll
        for (int i = 0; i < 4; i++) {
            acc[i][0] = fmaf(ca[i], hh0, acc[i][0]);
            acc[i][1] = fmaf(ca[i], hh1, acc[i][1]);
            acc[i][2] = fmaf(ca[i], hh2, acc[i][2]);
        }
    }

    #pragma unroll
    for (int i = 0; i < 4; i++) {
        float lam = Ls[tt + i];
        float* yr = g_Y + (size_t)(bl0 + tt + i)*DINNER + h*HEADDIM + pp;
        #pragma unroll
        for (int j = 0; j < 3; j++)
            yr[j] = fmaf(lam, acc[i][j], yr[j]);
    }
}

// ---------------- gated RMSNorm ------------------------------------------
__global__ __launch_bounds__(128)
void k_gated_rms(const float* __restrict__ norm_w) {
    int bl = blockIdx.x;
    int t  = threadIdx.x;
    int lane = t & 31, wid = t >> 5;
    __shared__ float sh[4];
    float v[3];
    float ss = 0.f;
    #pragma unroll
    for (int j = 0; j < 3; j++) {
        int d = t + j*128;
        float y = g_Y[(size_t)bl*DINNER + d];
        float z = g_ZX[(size_t)bl*DINPROJ + d];
        y *= z * sigf(z);
        v[j] = y;
        ss = fmaf(y, y, ss);
    }
    #pragma unroll
    for (int o = 16; o > 0; o >>= 1) ss += __shfl_xor_sync(0xffffffffu, ss, o);
    if (lane == 0) sh[wid] = ss;
    __syncthreads();
    ss = sh[0] + sh[1] + sh[2] + sh[3];
    float rms = rsqrtf(ss * (1.f/DINNER) + 1e-5f);
    #pragma unroll
    for (int j = 0; j < 3; j++) {
        int d = t + j*128;
        g_Y[(size_t)bl*DINNER + d] = v[j] * rms * norm_w[d];
    }
}

// ---------------- residual add + layernorm -> X --------------------------
__global__ __launch_bounds__(192)
void k_res_ln(const float* __restrict__ ln_w, const float* __restrict__ ln_b) {
    int bl = blockIdx.x;
    int d  = threadIdx.x;
    int lane = d & 31, wid = d >> 5;
    __shared__ float shs[6], shq[6];
    float x = g_O[(size_t)bl*DMODEL + d] + g_X[(size_t)bl*DMODEL + d];
    float s = x, q = x*x;
    #pragma unroll
    for (int o = 16; o > 0; o >>= 1) {
        s += __shfl_xor_sync(0xffffffffu, s, o);
        q += __shfl_xor_sync(0xffffffffu, q, o);
    }
    if (lane == 0) { shs[wid] = s; shq[wid] = q; }
    __syncthreads();
    s = 0.f; q = 0.f;
    #pragma unroll
    for (int i = 0; i < 6; i++) { s += shs[i]; q += shq[i]; }
    float mu  = s * (1.f/DMODEL);
    float var = q * (1.f/DMODEL) - mu*mu;
    g_X[(size_t)bl*DMODEL + d] = (x - mu) * rsqrtf(var + 1e-5f) * ln_w[d] + ln_b[d];
}

// ---------------- output linear ------------------------------------------
__global__ __launch_bounds__(192)
void k_final(const float* __restrict__ w, const float* __restrict__ bias,
             float* __restrict__ out) {
    int bl = blockIdx.x;
    int d  = threadIdx.x;
    int lane = d & 31, wid = d >> 5;
    int b = bl / SEQL, l = bl % SEQL;
    __shared__ float sh[6][4];
    float x = g_X[(size_t)bl*DMODEL + d];
    float p0 = x * w[0*DMODEL + d];
    float p1 = x * w[1*DMODEL + d];
    float p2 = x * w[2*DMODEL + d];
    float p3 = x * w[3*DMODEL + d];
    #pragma unroll
    for (int o = 16; o > 0; o >>= 1) {
        p0 += __shfl_xor_sync(0xffffffffu, p0, o);
        p1 += __shfl_xor_sync(0xffffffffu, p1, o);
        p2 += __shfl_xor_sync(0xffffffffu, p2, o);
        p3 += __shfl_xor_sync(0xffffffffu, p3, o);
    }
    if (lane == 0) { sh[wid][0]=p0; sh[wid][1]=p1; sh[wid][2]=p2; sh[wid][3]=p3; }
    __syncthreads();
    if (d < 4) {
        float s = 0.f;
        #pragma unroll
        for (int i = 0; i < 6; i++) s += sh[i][d];
        out[(size_t)b*4*SEQL + (size_t)d*SEQL + l] = s + bias[d];
    }
}

// ---------------- driver --------------------------------------------------
extern "C" void kernel_launch(void* const* d_in, const int* in_sizes, int n_in,
                              void* d_out, int out_size) {
    const float* inp      = (const float*)d_in[0];
    const float* lin_in_w = (const float*)d_in[1];
    const float* lin_in_b = (const float*)d_in[2];
    const float* in_w     = (const float*)d_in[3];
    const float* conv_w   = (const float*)d_in[4];
    const float* conv_b   = (const float*)d_in[5];
    const float* dt_bias  = (const float*)d_in[6];
    const float* A_log    = (const float*)d_in[7];
    const float* Dv       = (const float*)d_in[8];
    const float* norm_w   = (const float*)d_in[9];
    const float* out_w    = (const float*)d_in[10];
    const float* ln_w     = (const float*)d_in[11];
    const float* ln_b     = (const float*)d_in[12];
    const float* lo_w     = (const float*)d_in[13];
    const float* lo_b     = (const float*)d_in[14];
    float* out = (float*)d_out;

    static bool attr_set = false;
    if (!attr_set) {
        cudaFuncSetAttribute(k_mma, cudaFuncAttributeMaxDynamicSharedMemorySize,
                             (int)MMA_SMEM);
        cudaFuncSetAttribute(k_scan_blk, cudaFuncAttributeMaxDynamicSharedMemorySize,
                             (int)SCAN_SMEM);
        attr_set = true;
    }

    const int scan_blocks = BATCHN*NHEADS*NCHUNK;   // 2048
    const int corr_blocks = BATCHN*NHEADS*NCHUNK;

    k_lin_in<<<(BL*DMODEL + 255)/256, 256>>>(inp, lin_in_w, lin_in_b);

    for (int layer = 0; layer < NLAYERS; layer++) {
        const float* in_w_l = in_w + (size_t)layer*DINPROJ*DMODEL;
        // in_proj: 896 cols (7 exact tiles); dt via warp-dot in k_convdt
        k_mma<<<7*(BL/128), 256, MMA_SMEM>>>(in_w_l, 0, 896, DMODEL, DINPROJ);
        k_convdt<<<CONV_BLKS + DT_BLKS, 256>>>(
            conv_w + (size_t)layer*CONVDIM*4,
            conv_b + (size_t)layer*CONVDIM,
            dt_bias + layer*NHEADS,
            A_log + layer*NHEADS,
            in_w_l);
        k_scan_blk<<<scan_blocks, 384, SCAN_SMEM>>>(
            Dv + layer*NHEADS,
            conv_w + (size_t)layer*CONVDIM*4,
            conv_b + (size_t)layer*CONVDIM);
        k_chunk_seq<<<(BATCHN*NHEADS*HEADDIM*DSTATE + 255)/256, 256>>>();
        k_corr<<<corr_blocks, 256>>>();
        k_gated_rms<<<BL, 128>>>(norm_w + (size_t)layer*DINNER);
        k_mma<<<2*(BL/128), 256, MMA_SMEM>>>(
            out_w + (size_t)layer*DMODEL*DINNER, 1, DMODEL, DINNER, DMODEL);
        k_res_ln<<<BL, 192>>>(ln_w + (size_t)layer*DMODEL,
                              ln_b + (size_t)layer*DMODEL);
    }

    k_final<<<BL, 192>>>(lo_w, lo_b, out);
}